// round 1
// baseline (speedup 1.0000x reference)
#include <cuda_runtime.h>
#include <math.h>

// Problem constants
#define BB   2
#define SS   2048
#define DD   768
#define HH   12
#define HDD  64
#define MM   (BB * SS)        // 4096
#define NQKV (3 * DD)         // 2304
#define QKV_LD 2304

// Scratch (allocation-free rule: __device__ globals)
__device__ float g_qkv[MM * NQKV];    // [4096, 2304]
__device__ float g_attn[MM * DD];     // [4096, 768]

// ---------------------------------------------------------------------------
// SGEMM with bias: C[M,N] = A[M,K] @ B[K,N] + bias[N]
// 128x128 block tile, K-step 8, 256 threads, 8x8 per-thread micro-tile.
// Assumes M%128==0, N%128==0, K%8==0 (true for both call sites).
// ---------------------------------------------------------------------------
__global__ __launch_bounds__(256) void sgemm_bias_kernel(
    const float* __restrict__ A, const float* __restrict__ B,
    const float* __restrict__ bias, float* __restrict__ C,
    int M, int N, int K)
{
    __shared__ float As[8][132];   // transposed A tile: As[k][m]
    __shared__ float Bs[8][132];   // B tile row-major:  Bs[k][n]

    const int tid  = threadIdx.x;
    const int m0   = blockIdx.y * 128;
    const int n0   = blockIdx.x * 128;

    const int warp = tid >> 5, lane = tid & 31;
    const int row  = (warp >> 2) * 64 + (lane >> 2) * 8;   // 0..120
    const int col  = (warp &  3) * 32 + (lane &  3) * 8;   // 0..120

    const int am = tid >> 1, ak = (tid & 1) * 4;           // A load: 128 rows x 8 cols
    const int bk = tid >> 5, bn = (tid & 31) * 4;          // B load: 8 rows x 128 cols

    const float* Aptr = A + (size_t)(m0 + am) * K + ak;
    const float* Bptr = B + (size_t)bk * N + n0 + bn;

    float acc[8][8];
    #pragma unroll
    for (int i = 0; i < 8; i++)
        #pragma unroll
        for (int j = 0; j < 8; j++) acc[i][j] = 0.f;

    for (int k0 = 0; k0 < K; k0 += 8) {
        float4 a4 = *(const float4*)(Aptr + k0);
        float4 b4 = *(const float4*)(Bptr + (size_t)k0 * N);
        As[ak + 0][am] = a4.x;
        As[ak + 1][am] = a4.y;
        As[ak + 2][am] = a4.z;
        As[ak + 3][am] = a4.w;
        *(float4*)&Bs[bk][bn] = b4;
        __syncthreads();

        #pragma unroll
        for (int kk = 0; kk < 8; kk++) {
            float a[8], b[8];
            *(float4*)(a)     = *(const float4*)&As[kk][row];
            *(float4*)(a + 4) = *(const float4*)&As[kk][row + 4];
            *(float4*)(b)     = *(const float4*)&Bs[kk][col];
            *(float4*)(b + 4) = *(const float4*)&Bs[kk][col + 4];
            #pragma unroll
            for (int i = 0; i < 8; i++)
                #pragma unroll
                for (int j = 0; j < 8; j++)
                    acc[i][j] += a[i] * b[j];
        }
        __syncthreads();
    }

    #pragma unroll
    for (int i = 0; i < 8; i++) {
        float* Crow = C + (size_t)(m0 + row + i) * N + n0 + col;
        #pragma unroll
        for (int j = 0; j < 8; j++)
            Crow[j] = acc[i][j] + bias[n0 + col + j];
    }
}

// ---------------------------------------------------------------------------
// Flash attention, fp32, causal. One block = 64 query rows of one (b,h).
// 256 threads as 16x16; each thread owns a 4x4 tile of the 64x64 S / O tiles.
// smem: Qt[d][r], Kt[d][c] (transposed, stride 65), Vs[k][c], Pt[k][r].
// Online softmax with warp-half shuffle reductions (16 tx lanes per row group).
// ---------------------------------------------------------------------------
__global__ __launch_bounds__(256) void flash_kernel(
    const float* __restrict__ qkv, float* __restrict__ attn_out)
{
    extern __shared__ float sm[];
    float* Qt = sm;                 // 64*65
    float* Kt = sm + 64 * 65;       // 64*65
    float* Vs = sm + 2 * 64 * 65;   // 64*65
    float* Pt = sm + 3 * 64 * 65;   // 64*65

    const int tid = threadIdx.x;
    const int tx  = tid & 15;       // key-col / hd-col group
    const int ty  = tid >> 4;       // query-row group
    const int qi  = blockIdx.x;     // query tile 0..31
    const int bh  = blockIdx.y;     // 0..23
    const int b   = bh / HH, h = bh % HH;

    const float* qbase = qkv + ((size_t)b * SS + (size_t)qi * 64) * QKV_LD + h * HDD;
    const float* kbase = qkv + (size_t)b * SS * QKV_LD + DD + h * HDD;
    const float* vbase = kbase + DD;

    // Load Q tile transposed, pre-scaled by hd^-0.5 = 0.125
    #pragma unroll
    for (int it = 0; it < 4; it++) {
        int f = tid + it * 256;
        int r = f >> 4, d4 = (f & 15) * 4;
        float4 v = *(const float4*)(qbase + (size_t)r * QKV_LD + d4);
        Qt[(d4 + 0) * 65 + r] = v.x * 0.125f;
        Qt[(d4 + 1) * 65 + r] = v.y * 0.125f;
        Qt[(d4 + 2) * 65 + r] = v.z * 0.125f;
        Qt[(d4 + 3) * 65 + r] = v.w * 0.125f;
    }

    float o[4][4];
    float m_i[4], l_i[4];
    #pragma unroll
    for (int u = 0; u < 4; u++) {
        m_i[u] = -INFINITY; l_i[u] = 0.f;
        #pragma unroll
        for (int w = 0; w < 4; w++) o[u][w] = 0.f;
    }

    for (int j = 0; j <= qi; j++) {
        const float* kb = kbase + (size_t)j * 64 * QKV_LD;
        const float* vb = vbase + (size_t)j * 64 * QKV_LD;
        #pragma unroll
        for (int it = 0; it < 4; it++) {
            int f = tid + it * 256;
            int r = f >> 4, d4 = (f & 15) * 4;
            float4 kv = *(const float4*)(kb + (size_t)r * QKV_LD + d4);
            Kt[(d4 + 0) * 65 + r] = kv.x;
            Kt[(d4 + 1) * 65 + r] = kv.y;
            Kt[(d4 + 2) * 65 + r] = kv.z;
            Kt[(d4 + 3) * 65 + r] = kv.w;
            float4 vv = *(const float4*)(vb + (size_t)r * QKV_LD + d4);
            Vs[r * 65 + d4 + 0] = vv.x;
            Vs[r * 65 + d4 + 1] = vv.y;
            Vs[r * 65 + d4 + 2] = vv.z;
            Vs[r * 65 + d4 + 3] = vv.w;
        }
        __syncthreads();

        // S = (Q*scale) @ K^T : 4x4 per thread
        float s[4][4];
        #pragma unroll
        for (int u = 0; u < 4; u++)
            #pragma unroll
            for (int w = 0; w < 4; w++) s[u][w] = 0.f;

        for (int d = 0; d < 64; d++) {
            float q[4], k4[4];
            #pragma unroll
            for (int u = 0; u < 4; u++) q[u]  = Qt[d * 65 + ty * 4 + u];
            #pragma unroll
            for (int w = 0; w < 4; w++) k4[w] = Kt[d * 65 + tx * 4 + w];
            #pragma unroll
            for (int u = 0; u < 4; u++)
                #pragma unroll
                for (int w = 0; w < 4; w++)
                    s[u][w] += q[u] * k4[w];
        }

        if (j == qi) {
            #pragma unroll
            for (int u = 0; u < 4; u++)
                #pragma unroll
                for (int w = 0; w < 4; w++)
                    if (tx * 4 + w > ty * 4 + u) s[u][w] = -INFINITY;
        }

        // Online softmax (row reductions across 16 tx lanes = one warp half)
        #pragma unroll
        for (int u = 0; u < 4; u++) {
            float mloc = fmaxf(fmaxf(s[u][0], s[u][1]), fmaxf(s[u][2], s[u][3]));
            #pragma unroll
            for (int off = 8; off; off >>= 1)
                mloc = fmaxf(mloc, __shfl_xor_sync(0xffffffffu, mloc, off));
            float mn = fmaxf(m_i[u], mloc);
            float al = __expf(m_i[u] - mn);
            float lloc = 0.f;
            #pragma unroll
            for (int w = 0; w < 4; w++) {
                float pv = __expf(s[u][w] - mn);
                s[u][w] = pv;
                lloc += pv;
            }
            #pragma unroll
            for (int off = 8; off; off >>= 1)
                lloc += __shfl_xor_sync(0xffffffffu, lloc, off);
            l_i[u] = l_i[u] * al + lloc;
            m_i[u] = mn;
            #pragma unroll
            for (int w = 0; w < 4; w++) o[u][w] *= al;
        }

        // Stage P transposed for the PV rank-1 loop
        #pragma unroll
        for (int u = 0; u < 4; u++)
            #pragma unroll
            for (int w = 0; w < 4; w++)
                Pt[(tx * 4 + w) * 65 + ty * 4 + u] = s[u][w];
        __syncthreads();

        // O += P @ V
        for (int k = 0; k < 64; k++) {
            float p4[4], v4[4];
            #pragma unroll
            for (int u = 0; u < 4; u++) p4[u] = Pt[k * 65 + ty * 4 + u];
            #pragma unroll
            for (int w = 0; w < 4; w++) v4[w] = Vs[k * 65 + tx * 4 + w];
            #pragma unroll
            for (int u = 0; u < 4; u++)
                #pragma unroll
                for (int w = 0; w < 4; w++)
                    o[u][w] += p4[u] * v4[w];
        }
        __syncthreads();
    }

    // Normalize and write to [b*S + s, h*64 + d] layout
    float* obase = attn_out + ((size_t)b * SS + (size_t)qi * 64) * DD + h * HDD;
    #pragma unroll
    for (int u = 0; u < 4; u++) {
        float inv = 1.f / l_i[u];
        #pragma unroll
        for (int w = 0; w < 4; w++)
            obase[(size_t)(ty * 4 + u) * DD + tx * 4 + w] = o[u][w] * inv;
    }
}

// ---------------------------------------------------------------------------
// Launch
// ---------------------------------------------------------------------------
extern "C" void kernel_launch(void* const* d_in, const int* in_sizes, int n_in,
                              void* d_out, int out_size)
{
    const float* X    = (const float*)d_in[0];   // [2, 2048, 768]
    const float* Wqkv = (const float*)d_in[1];   // [768, 2304]
    const float* bqkv = (const float*)d_in[2];   // [2304]
    const float* Wout = (const float*)d_in[3];   // [768, 768]
    const float* bout = (const float*)d_in[4];   // [768]
    float* out = (float*)d_out;                  // [2, 2048, 768]

    float* qkv = nullptr;
    float* attn = nullptr;
    cudaGetSymbolAddress((void**)&qkv, g_qkv);
    cudaGetSymbolAddress((void**)&attn, g_attn);

    // 1) QKV = X @ Wqkv + bqkv
    {
        dim3 grid(NQKV / 128, MM / 128);   // (18, 32)
        sgemm_bias_kernel<<<grid, 256>>>(X, Wqkv, bqkv, qkv, MM, NQKV, DD);
    }

    // 2) Flash attention per (b, h), 64-query tiles
    {
        const int smem = 4 * 64 * 65 * (int)sizeof(float);   // 66560 B
        cudaFuncSetAttribute(flash_kernel,
                             cudaFuncAttributeMaxDynamicSharedMemorySize, smem);
        dim3 grid(SS / 64, BB * HH);       // (32, 24)
        flash_kernel<<<grid, 256, smem>>>(qkv, attn);
    }

    // 3) out = attn @ Wout + bout
    {
        dim3 grid(DD / 128, MM / 128);     // (6, 32)
        sgemm_bias_kernel<<<grid, 256>>>(attn, Wout, bout, out, MM, DD, DD);
    }
}

// round 2
// speedup vs baseline: 1.1642x; 1.1642x over previous
#include <cuda_runtime.h>
#include <math.h>

// Problem constants
#define BB   2
#define SS   2048
#define DD   768
#define HH   12
#define HDD  64
#define MM   (BB * SS)        // 4096
#define NQKV (3 * DD)         // 2304
#define QKV_LD 2304

// Scratch (allocation-free rule: __device__ globals)
__device__ float g_qkv[MM * NQKV];    // [4096, 2304]
__device__ float g_attn[MM * DD];     // [4096, 768]

// ---------------------------------------------------------------------------
// tf32 helpers: 3xTF32 compensated products recover ~fp32 accuracy.
// ---------------------------------------------------------------------------
__device__ __forceinline__ void tf32split(float x, float& hi, float& lo) {
    unsigned u;
    asm("cvt.rna.tf32.f32 %0, %1;" : "=r"(u) : "f"(x));
    hi = __uint_as_float(u);
    float r = x - hi;
    asm("cvt.rna.tf32.f32 %0, %1;" : "=r"(u) : "f"(r));
    lo = __uint_as_float(u);
}

__device__ __forceinline__ void mma_tf32(float* c,
                                         float a0, float a1, float a2, float a3,
                                         float b0, float b1) {
    unsigned A0 = __float_as_uint(a0), A1 = __float_as_uint(a1);
    unsigned A2 = __float_as_uint(a2), A3 = __float_as_uint(a3);
    unsigned B0 = __float_as_uint(b0), B1 = __float_as_uint(b1);
    asm volatile(
        "mma.sync.aligned.m16n8k8.row.col.f32.tf32.tf32.f32 "
        "{%0,%1,%2,%3}, {%4,%5,%6,%7}, {%8,%9}, {%0,%1,%2,%3};\n"
        : "+f"(c[0]), "+f"(c[1]), "+f"(c[2]), "+f"(c[3])
        : "r"(A0), "r"(A1), "r"(A2), "r"(A3), "r"(B0), "r"(B1));
}

// ---------------------------------------------------------------------------
// GEMM (tf32 x3): C[M,N] = A[M,K] @ B[K,N] + bias[N]
// Block tile 128x128, K-step 32, 256 threads = 8 warps (2m x 4n), warp 64x32.
// smem A stored transposed [k][m] stride 136; B [k][n] stride 136
// (136 % 32 == 8 -> conflict-free quad fragment loads).
// ---------------------------------------------------------------------------
#define GSTR 136
__global__ __launch_bounds__(256) void gemm_tf32_kernel(
    const float* __restrict__ A, const float* __restrict__ B,
    const float* __restrict__ bias, float* __restrict__ C,
    int M, int N, int K)
{
    extern __shared__ float smg[];
    float* Ah = smg;                 // [32][136]
    float* Al = Ah + 32 * GSTR;
    float* Bh = Al + 32 * GSTR;      // [32][136]
    float* Bl = Bh + 32 * GSTR;

    const int tid  = threadIdx.x;
    const int lane = tid & 31, warp = tid >> 5;
    const int g = lane >> 2, t = lane & 3;
    const int m0 = blockIdx.y * 128, n0 = blockIdx.x * 128;
    const int wm = (warp >> 2) * 64, wn = (warp & 3) * 32;

    const int ar = tid >> 3;          // A row base (0..31), +32*i
    const int ac = (tid & 7) * 4;     // A k-col group
    const int br = tid >> 5;          // B k-row base, +8*i
    const int bc = (tid & 31) * 4;    // B n-col group

    float acc[4][4][4];
    #pragma unroll
    for (int mt = 0; mt < 4; mt++)
        #pragma unroll
        for (int nt = 0; nt < 4; nt++)
            #pragma unroll
            for (int r = 0; r < 4; r++) acc[mt][nt][r] = 0.f;

    for (int kb = 0; kb < K; kb += 32) {
        // Stage A (coalesced 128B/row) -> transposed hi/lo
        #pragma unroll
        for (int i = 0; i < 4; i++) {
            int mrow = ar + 32 * i;
            float4 v = *(const float4*)(A + (size_t)(m0 + mrow) * K + kb + ac);
            float h, l;
            tf32split(v.x, h, l); Ah[(ac + 0) * GSTR + mrow] = h; Al[(ac + 0) * GSTR + mrow] = l;
            tf32split(v.y, h, l); Ah[(ac + 1) * GSTR + mrow] = h; Al[(ac + 1) * GSTR + mrow] = l;
            tf32split(v.z, h, l); Ah[(ac + 2) * GSTR + mrow] = h; Al[(ac + 2) * GSTR + mrow] = l;
            tf32split(v.w, h, l); Ah[(ac + 3) * GSTR + mrow] = h; Al[(ac + 3) * GSTR + mrow] = l;
        }
        // Stage B (coalesced 512B/warp) -> hi/lo
        #pragma unroll
        for (int i = 0; i < 4; i++) {
            int krow = br + 8 * i;
            float4 v = *(const float4*)(B + (size_t)(kb + krow) * N + n0 + bc);
            float4 h4, l4;
            tf32split(v.x, h4.x, l4.x);
            tf32split(v.y, h4.y, l4.y);
            tf32split(v.z, h4.z, l4.z);
            tf32split(v.w, h4.w, l4.w);
            *(float4*)&Bh[krow * GSTR + bc] = h4;
            *(float4*)&Bl[krow * GSTR + bc] = l4;
        }
        __syncthreads();

        #pragma unroll
        for (int kk = 0; kk < 4; kk++) {
            float ah[4][4], al_[4][4];
            #pragma unroll
            for (int mt = 0; mt < 4; mt++) {
                int mrow = wm + mt * 16 + g;
                int k0 = (kk * 8 + t) * GSTR, k1 = (kk * 8 + t + 4) * GSTR;
                ah[mt][0]  = Ah[k0 + mrow];     ah[mt][1]  = Ah[k0 + mrow + 8];
                ah[mt][2]  = Ah[k1 + mrow];     ah[mt][3]  = Ah[k1 + mrow + 8];
                al_[mt][0] = Al[k0 + mrow];     al_[mt][1] = Al[k0 + mrow + 8];
                al_[mt][2] = Al[k1 + mrow];     al_[mt][3] = Al[k1 + mrow + 8];
            }
            #pragma unroll
            for (int nt = 0; nt < 4; nt++) {
                int nc = wn + nt * 8 + g;
                int k0 = (kk * 8 + t) * GSTR, k1 = (kk * 8 + t + 4) * GSTR;
                float bh0 = Bh[k0 + nc], bh1 = Bh[k1 + nc];
                float bl0 = Bl[k0 + nc], bl1 = Bl[k1 + nc];
                #pragma unroll
                for (int mt = 0; mt < 4; mt++) {
                    mma_tf32(acc[mt][nt], ah[mt][0], ah[mt][1], ah[mt][2], ah[mt][3], bh0, bh1);
                    mma_tf32(acc[mt][nt], ah[mt][0], ah[mt][1], ah[mt][2], ah[mt][3], bl0, bl1);
                    mma_tf32(acc[mt][nt], al_[mt][0], al_[mt][1], al_[mt][2], al_[mt][3], bh0, bh1);
                }
            }
        }
        __syncthreads();
    }

    // Epilogue with bias
    #pragma unroll
    for (int mt = 0; mt < 4; mt++) {
        int r0 = m0 + wm + mt * 16 + g;
        #pragma unroll
        for (int nt = 0; nt < 4; nt++) {
            int c0 = n0 + wn + nt * 8 + 2 * t;
            float b0 = bias[c0], b1 = bias[c0 + 1];
            C[(size_t)r0 * N + c0]           = acc[mt][nt][0] + b0;
            C[(size_t)r0 * N + c0 + 1]       = acc[mt][nt][1] + b1;
            C[(size_t)(r0 + 8) * N + c0]     = acc[mt][nt][2] + b0;
            C[(size_t)(r0 + 8) * N + c0 + 1] = acc[mt][nt][3] + b1;
        }
    }
}

// ---------------------------------------------------------------------------
// Flash attention with tf32x3 mma. One block = 64 queries of one (b,h).
// 256 threads = 8 warps (4m x 2n), warp tile 16x32 for both QK^T and PV.
// Q kept in registers (hi/lo frags); K/V/P staged hi/lo in smem, stride 72.
// Online softmax: thread = (row = tid>>2, 16-col segment = tid&3).
// ---------------------------------------------------------------------------
#define FSTR 72
__global__ __launch_bounds__(256) void flash_mma_kernel(
    const float* __restrict__ qkv, float* __restrict__ attn_out)
{
    extern __shared__ float smf[];
    float* Kh = smf;                  // [64][72]
    float* Kl = Kh + 64 * FSTR;
    float* Vh = Kl + 64 * FSTR;
    float* Vl = Vh + 64 * FSTR;
    float* Ph = Vl + 64 * FSTR;       // raw S, then p_hi
    float* Pl = Ph + 64 * FSTR;       // p_lo
    float* alpha_s = Pl + 64 * FSTR;  // [64]
    float* l_s     = alpha_s + 64;    // [64]

    const int tid  = threadIdx.x;
    const int lane = tid & 31, warp = tid >> 5;
    const int g = lane >> 2, t = lane & 3;
    const int wm = (warp >> 1) * 16;  // {0,16,32,48}
    const int wn = (warp & 1) * 32;   // {0,32}

    const int qi = blockIdx.x;        // query tile 0..31
    const int bh = blockIdx.y;
    const int b  = bh / HH, h = bh % HH;

    const float* qbase = qkv + ((size_t)b * SS + (size_t)qi * 64) * QKV_LD + h * HDD;
    const float* kbase = qkv + (size_t)b * SS * QKV_LD + DD + h * HDD;
    const float* vbase = kbase + DD;

    const int sr = tid >> 2;          // staging/softmax row 0..63
    const int sc = (tid & 3) * 4;     // staging col group (+16*i)

    // ---- Stage Q (scaled) into Ph, then load Q fragments into registers ----
    #pragma unroll
    for (int i = 0; i < 4; i++) {
        int col = sc + 16 * i;
        float4 v = *(const float4*)(qbase + (size_t)sr * QKV_LD + col);
        Ph[sr * FSTR + col + 0] = v.x * 0.125f;
        Ph[sr * FSTR + col + 1] = v.y * 0.125f;
        Ph[sr * FSTR + col + 2] = v.z * 0.125f;
        Ph[sr * FSTR + col + 3] = v.w * 0.125f;
    }
    __syncthreads();

    float qh[8][4], ql[8][4];
    #pragma unroll
    for (int kk = 0; kk < 8; kk++) {
        int r0 = (wm + g) * FSTR, r1 = (wm + 8 + g) * FSTR;
        int c0 = kk * 8 + t, c1 = kk * 8 + t + 4;
        tf32split(Ph[r0 + c0], qh[kk][0], ql[kk][0]);
        tf32split(Ph[r1 + c0], qh[kk][1], ql[kk][1]);
        tf32split(Ph[r0 + c1], qh[kk][2], ql[kk][2]);
        tf32split(Ph[r1 + c1], qh[kk][3], ql[kk][3]);
    }
    __syncthreads();   // Ph will be reused for S/P

    float o[4][4];
    #pragma unroll
    for (int nt = 0; nt < 4; nt++)
        #pragma unroll
        for (int r = 0; r < 4; r++) o[nt][r] = 0.f;
    float m_i = -INFINITY, l_i = 0.f;

    for (int j = 0; j <= qi; j++) {
        const float* kb = kbase + (size_t)j * 64 * QKV_LD;
        const float* vb = vbase + (size_t)j * 64 * QKV_LD;

        // ---- Stage K, V (hi/lo) ----
        #pragma unroll
        for (int i = 0; i < 4; i++) {
            int col = sc + 16 * i;
            float4 kv = *(const float4*)(kb + (size_t)sr * QKV_LD + col);
            float h0, l0;
            tf32split(kv.x, h0, l0); Kh[sr * FSTR + col + 0] = h0; Kl[sr * FSTR + col + 0] = l0;
            tf32split(kv.y, h0, l0); Kh[sr * FSTR + col + 1] = h0; Kl[sr * FSTR + col + 1] = l0;
            tf32split(kv.z, h0, l0); Kh[sr * FSTR + col + 2] = h0; Kl[sr * FSTR + col + 2] = l0;
            tf32split(kv.w, h0, l0); Kh[sr * FSTR + col + 3] = h0; Kl[sr * FSTR + col + 3] = l0;
            float4 vv = *(const float4*)(vb + (size_t)sr * QKV_LD + col);
            tf32split(vv.x, h0, l0); Vh[sr * FSTR + col + 0] = h0; Vl[sr * FSTR + col + 0] = l0;
            tf32split(vv.y, h0, l0); Vh[sr * FSTR + col + 1] = h0; Vl[sr * FSTR + col + 1] = l0;
            tf32split(vv.z, h0, l0); Vh[sr * FSTR + col + 2] = h0; Vl[sr * FSTR + col + 2] = l0;
            tf32split(vv.w, h0, l0); Vh[sr * FSTR + col + 3] = h0; Vl[sr * FSTR + col + 3] = l0;
        }
        __syncthreads();

        // ---- S = Q @ K^T (tf32x3) ----
        float s4[4][4];
        #pragma unroll
        for (int nt = 0; nt < 4; nt++)
            #pragma unroll
            for (int r = 0; r < 4; r++) s4[nt][r] = 0.f;

        #pragma unroll
        for (int kk = 0; kk < 8; kk++) {
            int c0 = kk * 8 + t, c1 = kk * 8 + t + 4;
            #pragma unroll
            for (int nt = 0; nt < 4; nt++) {
                int nrow = (wn + nt * 8 + g) * FSTR;
                float bh0 = Kh[nrow + c0], bh1 = Kh[nrow + c1];
                float bl0 = Kl[nrow + c0], bl1 = Kl[nrow + c1];
                mma_tf32(s4[nt], qh[kk][0], qh[kk][1], qh[kk][2], qh[kk][3], bh0, bh1);
                mma_tf32(s4[nt], qh[kk][0], qh[kk][1], qh[kk][2], qh[kk][3], bl0, bl1);
                mma_tf32(s4[nt], ql[kk][0], ql[kk][1], ql[kk][2], ql[kk][3], bh0, bh1);
            }
        }

        // ---- Write raw S to Ph ----
        #pragma unroll
        for (int nt = 0; nt < 4; nt++) {
            int c0 = wn + nt * 8 + 2 * t;
            Ph[(wm + g) * FSTR + c0]         = s4[nt][0];
            Ph[(wm + g) * FSTR + c0 + 1]     = s4[nt][1];
            Ph[(wm + 8 + g) * FSTR + c0]     = s4[nt][2];
            Ph[(wm + 8 + g) * FSTR + c0 + 1] = s4[nt][3];
        }
        __syncthreads();

        // ---- Online softmax (thread owns row sr, cols [4*(tid&3)*4 .. +15]) --
        {
            float sv[16];
            int cbase = (tid & 3) * 16;
            #pragma unroll
            for (int i = 0; i < 4; i++) {
                float4 v = *(const float4*)&Ph[sr * FSTR + cbase + 4 * i];
                sv[4 * i + 0] = v.x; sv[4 * i + 1] = v.y;
                sv[4 * i + 2] = v.z; sv[4 * i + 3] = v.w;
            }
            if (j == qi) {
                #pragma unroll
                for (int i = 0; i < 16; i++)
                    if (cbase + i > sr) sv[i] = -INFINITY;
            }
            float mloc = -INFINITY;
            #pragma unroll
            for (int i = 0; i < 16; i++) mloc = fmaxf(mloc, sv[i]);
            mloc = fmaxf(mloc, __shfl_xor_sync(0xffffffffu, mloc, 1));
            mloc = fmaxf(mloc, __shfl_xor_sync(0xffffffffu, mloc, 2));
            float mn = fmaxf(m_i, mloc);
            float al = __expf(m_i - mn);
            m_i = mn;
            float lsum = 0.f;
            #pragma unroll
            for (int i = 0; i < 16; i++) {
                float p = __expf(sv[i] - mn);
                lsum += p;
                float ph, pl;
                tf32split(p, ph, pl);
                Ph[sr * FSTR + cbase + i] = ph;
                Pl[sr * FSTR + cbase + i] = pl;
            }
            lsum += __shfl_xor_sync(0xffffffffu, lsum, 1);
            lsum += __shfl_xor_sync(0xffffffffu, lsum, 2);
            l_i = l_i * al + lsum;
            if ((tid & 3) == 0) alpha_s[sr] = al;
        }
        __syncthreads();

        // ---- Rescale O, then O += P @ V (tf32x3) ----
        {
            float a0 = alpha_s[wm + g], a1 = alpha_s[wm + 8 + g];
            #pragma unroll
            for (int nt = 0; nt < 4; nt++) {
                o[nt][0] *= a0; o[nt][1] *= a0;
                o[nt][2] *= a1; o[nt][3] *= a1;
            }
        }
        #pragma unroll
        for (int kk = 0; kk < 8; kk++) {
            int c0 = kk * 8 + t, c1 = kk * 8 + t + 4;
            int r0 = (wm + g) * FSTR, r1 = (wm + 8 + g) * FSTR;
            float pa0h = Ph[r0 + c0], pa1h = Ph[r1 + c0];
            float pa2h = Ph[r0 + c1], pa3h = Ph[r1 + c1];
            float pa0l = Pl[r0 + c0], pa1l = Pl[r1 + c0];
            float pa2l = Pl[r0 + c1], pa3l = Pl[r1 + c1];
            int k0 = (kk * 8 + t) * FSTR, k1 = (kk * 8 + t + 4) * FSTR;
            #pragma unroll
            for (int nt = 0; nt < 4; nt++) {
                int nc = wn + nt * 8 + g;
                float bh0 = Vh[k0 + nc], bh1 = Vh[k1 + nc];
                float bl0 = Vl[k0 + nc], bl1 = Vl[k1 + nc];
                mma_tf32(o[nt], pa0h, pa1h, pa2h, pa3h, bh0, bh1);
                mma_tf32(o[nt], pa0h, pa1h, pa2h, pa3h, bl0, bl1);
                mma_tf32(o[nt], pa0l, pa1l, pa2l, pa3l, bh0, bh1);
            }
        }
        __syncthreads();
    }

    // ---- Finalize: divide by l, write out ----
    if ((tid & 3) == 0) l_s[sr] = l_i;
    __syncthreads();
    {
        float inv0 = 1.f / l_s[wm + g];
        float inv1 = 1.f / l_s[wm + 8 + g];
        float* obase = attn_out + ((size_t)b * SS + (size_t)qi * 64) * DD + h * HDD;
        #pragma unroll
        for (int nt = 0; nt < 4; nt++) {
            int c0 = wn + nt * 8 + 2 * t;
            obase[(size_t)(wm + g) * DD + c0]         = o[nt][0] * inv0;
            obase[(size_t)(wm + g) * DD + c0 + 1]     = o[nt][1] * inv0;
            obase[(size_t)(wm + 8 + g) * DD + c0]     = o[nt][2] * inv1;
            obase[(size_t)(wm + 8 + g) * DD + c0 + 1] = o[nt][3] * inv1;
        }
    }
}

// ---------------------------------------------------------------------------
// Launch
// ---------------------------------------------------------------------------
extern "C" void kernel_launch(void* const* d_in, const int* in_sizes, int n_in,
                              void* d_out, int out_size)
{
    const float* X    = (const float*)d_in[0];   // [2, 2048, 768]
    const float* Wqkv = (const float*)d_in[1];   // [768, 2304]
    const float* bqkv = (const float*)d_in[2];   // [2304]
    const float* Wout = (const float*)d_in[3];   // [768, 768]
    const float* bout = (const float*)d_in[4];   // [768]
    float* out = (float*)d_out;                  // [2, 2048, 768]

    float* qkv = nullptr;
    float* attn = nullptr;
    cudaGetSymbolAddress((void**)&qkv, g_qkv);
    cudaGetSymbolAddress((void**)&attn, g_attn);

    const int gemm_smem  = 4 * 32 * GSTR * (int)sizeof(float);          // 69632
    const int flash_smem = (6 * 64 * FSTR + 128) * (int)sizeof(float);  // 111104

    cudaFuncSetAttribute(gemm_tf32_kernel,
                         cudaFuncAttributeMaxDynamicSharedMemorySize, gemm_smem);
    cudaFuncSetAttribute(flash_mma_kernel,
                         cudaFuncAttributeMaxDynamicSharedMemorySize, flash_smem);

    // 1) QKV = X @ Wqkv + bqkv
    {
        dim3 grid(NQKV / 128, MM / 128);   // (18, 32)
        gemm_tf32_kernel<<<grid, 256, gemm_smem>>>(X, Wqkv, bqkv, qkv, MM, NQKV, DD);
    }

    // 2) Flash attention per (b, h), 64-query tiles
    {
        dim3 grid(SS / 64, BB * HH);       // (32, 24)
        flash_mma_kernel<<<grid, 256, flash_smem>>>(qkv, attn);
    }

    // 3) out = attn @ Wout + bout
    {
        dim3 grid(DD / 128, MM / 128);     // (6, 32)
        gemm_tf32_kernel<<<grid, 256, gemm_smem>>>(attn, Wout, bout, out, MM, DD, DD);
    }
}

// round 4
// speedup vs baseline: 2.7815x; 2.3892x over previous
#include <cuda_runtime.h>
#include <cuda_bf16.h>
#include <math.h>
#include <cstdint>

// Problem constants
#define BB   2
#define SS   2048
#define DD   768
#define HH   12
#define HDD  64
#define MM   (BB * SS)        // 4096
#define NQKV (3 * DD)         // 2304

typedef __nv_bfloat16 bf16;

// Scratch (__device__ globals; no allocation allowed)
__device__ bf16 g_qkvh[MM * NQKV];
__device__ bf16 g_qkvl[MM * NQKV];
__device__ bf16 g_attnh[MM * DD];
__device__ bf16 g_attnl[MM * DD];
__device__ bf16 g_Xh[MM * DD];
__device__ bf16 g_Xl[MM * DD];
__device__ bf16 g_Bqh[NQKV * DD];
__device__ bf16 g_Bql[NQKV * DD];
__device__ bf16 g_Boh[DD * DD];
__device__ bf16 g_Bol[DD * DD];

// ---------------------------------------------------------------------------
// Helpers
// ---------------------------------------------------------------------------
__device__ __forceinline__ uint32_t smem_u32(const void* p) {
    uint32_t a;
    asm("{ .reg .u64 t; cvta.to.shared.u64 t, %1; cvt.u32.u64 %0, t; }" : "=r"(a) : "l"(p));
    return a;
}

__device__ __forceinline__ float ex2f(float x) {
    float r;
    asm("ex2.approx.ftz.f32 %0, %1;" : "=f"(r) : "f"(x));
    return r;
}

// pack two floats to bf16x2 (lo -> lower 16 bits, hi -> upper), rn rounding
__device__ __forceinline__ uint32_t cvt_pack_bf16(float lo, float hi) {
    uint32_t r;
    asm("cvt.rn.bf16x2.f32 %0, %1, %2;" : "=r"(r) : "f"(hi), "f"(lo));
    return r;
}

// split (x0,x1) into packed hi-pair (truncated bf16) and packed lo-pair (residual)
__device__ __forceinline__ void packsplit(float x0, float x1, uint32_t& hi, uint32_t& lo) {
    uint32_t u0 = __float_as_uint(x0) & 0xFFFF0000u;
    uint32_t u1 = __float_as_uint(x1) & 0xFFFF0000u;
    uint32_t h;
    asm("prmt.b32 %0, %1, %2, 0x7632;" : "=r"(h) : "r"(u0), "r"(u1));
    hi = h;
    float r0 = x0 - __uint_as_float(u0);
    float r1 = x1 - __uint_as_float(u1);
    lo = cvt_pack_bf16(r0, r1);
}

__device__ __forceinline__ void mma16816(float* c,
                                         uint32_t a0, uint32_t a1, uint32_t a2, uint32_t a3,
                                         uint32_t b0, uint32_t b1) {
    asm volatile(
        "mma.sync.aligned.m16n8k16.row.col.f32.bf16.bf16.f32 "
        "{%0,%1,%2,%3}, {%4,%5,%6,%7}, {%8,%9}, {%0,%1,%2,%3};\n"
        : "+f"(c[0]), "+f"(c[1]), "+f"(c[2]), "+f"(c[3])
        : "r"(a0), "r"(a1), "r"(a2), "r"(a3), "r"(b0), "r"(b1));
}

__device__ __forceinline__ void ldsm4t(uint32_t* r, uint32_t saddr) {
    asm volatile("ldmatrix.sync.aligned.m8n8.x4.trans.shared.b16 {%0,%1,%2,%3}, [%4];"
                 : "=r"(r[0]), "=r"(r[1]), "=r"(r[2]), "=r"(r[3]) : "r"(saddr));
}

__device__ __forceinline__ void cp16(uint32_t dst, const void* src) {
    asm volatile("cp.async.cg.shared.global [%0], [%1], 16;" :: "r"(dst), "l"(src));
}
#define CP_COMMIT() asm volatile("cp.async.commit_group;" ::: "memory")
#define CP_WAIT0()  asm volatile("cp.async.wait_group 0;" ::: "memory")
#define CP_WAIT1()  asm volatile("cp.async.wait_group 1;" ::: "memory")

// ---------------------------------------------------------------------------
// Prep kernels
// ---------------------------------------------------------------------------
__global__ void split_pair_kernel(const float* __restrict__ x,
                                  bf16* __restrict__ h, bf16* __restrict__ l, int n4)
{
    int i = blockIdx.x * blockDim.x + threadIdx.x;
    if (i < n4) {
        float4 v = ((const float4*)x)[i];
        uint32_t h01, l01, h23, l23;
        packsplit(v.x, v.y, h01, l01);
        packsplit(v.z, v.w, h23, l23);
        ((uint2*)h)[i] = make_uint2(h01, h23);
        ((uint2*)l)[i] = make_uint2(l01, l23);
    }
}

// W [K,N] fp32 -> Th/Tl [N,K] bf16 (transpose + split)
__global__ void transpose_split_kernel(const float* __restrict__ W,
                                       bf16* __restrict__ Th, bf16* __restrict__ Tl,
                                       int Kd, int Nd)
{
    __shared__ float tile[32][33];
    int n0 = blockIdx.x * 32, k0 = blockIdx.y * 32;
    int tx = threadIdx.x, ty = threadIdx.y;   // (32, 8)
    #pragma unroll
    for (int i = 0; i < 4; i++)
        tile[ty + i * 8][tx] = W[(size_t)(k0 + ty + i * 8) * Nd + n0 + tx];   // tile[k][n]
    __syncthreads();
    int idx = ty * 32 + tx;
    int n = idx >> 3, kp = idx & 7;
    #pragma unroll
    for (int w = 0; w < 2; w++) {
        int k2 = (kp + w * 8) * 2;
        uint32_t hh, ll;
        packsplit(tile[k2][n], tile[k2 + 1][n], hh, ll);
        *(uint32_t*)(Th + (size_t)(n0 + n) * Kd + k0 + k2) = hh;
        *(uint32_t*)(Tl + (size_t)(n0 + n) * Kd + k0 + k2) = ll;
    }
}

// ---------------------------------------------------------------------------
// GEMM (3xBF16): C[M,N] = A[M,K] @ Bt[N,K]^T + bias
// 128x128 block, K-chunk 32, 256 thr = 8 warps (2m x 4n), warp 64x32.
// cp.async double buffer; smem rows stride 40 bf16 (80B, 16B-aligned, bank-clean).
// SPLIT_OUT: write C as bf16 hi/lo arrays instead of fp32.
// ---------------------------------------------------------------------------
#define ASTR 40
#define TILEE (128 * ASTR)        // 5120 bf16 elems per array per buffer
#define ABYTES (TILEE * 2)        // 10240

template<bool SPLIT_OUT>
__global__ __launch_bounds__(256) void gemm_bf16_kernel(
    const bf16* __restrict__ Ah_g, const bf16* __restrict__ Al_g,
    const bf16* __restrict__ Bh_g, const bf16* __restrict__ Bl_g,
    const float* __restrict__ bias,
    float* __restrict__ C, bf16* __restrict__ Ch, bf16* __restrict__ Cl,
    int M, int N, int K)
{
    extern __shared__ bf16 smb[];
    const uint32_t sm0 = smem_u32(smb);

    const int tid = threadIdx.x;
    const int lane = tid & 31, warp = tid >> 5;
    const int g = lane >> 2, t = lane & 3;
    const int m0 = blockIdx.y * 128, n0 = blockIdx.x * 128;
    const int wm = (warp >> 2) * 64, wn = (warp & 3) * 32;

    float acc[4][4][4];
    #pragma unroll
    for (int mt = 0; mt < 4; mt++)
        #pragma unroll
        for (int nt = 0; nt < 4; nt++)
            #pragma unroll
            for (int r = 0; r < 4; r++) acc[mt][nt][r] = 0.f;

    const int NCH = K / 32;   // 24

    auto stage = [&](int ch) {
        const int kb = ch * 32;
        const uint32_t bb = sm0 + (ch & 1) * 4 * ABYTES;
        #pragma unroll
        for (int i = 0; i < 2; i++) {
            int idx = tid + i * 256;
            int r = idx >> 2, cc = idx & 3;
            uint32_t doff = r * 80 + cc * 16;
            cp16(bb + doff,              Ah_g + (size_t)(m0 + r) * K + kb + cc * 8);
            cp16(bb + ABYTES + doff,     Al_g + (size_t)(m0 + r) * K + kb + cc * 8);
            cp16(bb + 2 * ABYTES + doff, Bh_g + (size_t)(n0 + r) * K + kb + cc * 8);
            cp16(bb + 3 * ABYTES + doff, Bl_g + (size_t)(n0 + r) * K + kb + cc * 8);
        }
        CP_COMMIT();
    };

    stage(0);
    stage(1);

    for (int c = 0; c < NCH; c++) {
        if (c == NCH - 1) { CP_WAIT0(); } else { CP_WAIT1(); }
        __syncthreads();

        const bf16* bA_h = smb + (size_t)(c & 1) * 4 * TILEE;
        const bf16* bA_l = bA_h + TILEE;
        const bf16* bB_h = bA_h + 2 * TILEE;
        const bf16* bB_l = bA_h + 3 * TILEE;

        #pragma unroll
        for (int st = 0; st < 2; st++) {
            const int k0 = st * 16;
            uint32_t bh[4][2], bl[4][2];
            #pragma unroll
            for (int nt = 0; nt < 4; nt++) {
                const bf16* kr = bB_h + (wn + nt * 8 + g) * ASTR + k0 + 2 * t;
                bh[nt][0] = *(const uint32_t*)kr;
                bh[nt][1] = *(const uint32_t*)(kr + 8);
                const bf16* kl = bB_l + (wn + nt * 8 + g) * ASTR + k0 + 2 * t;
                bl[nt][0] = *(const uint32_t*)kl;
                bl[nt][1] = *(const uint32_t*)(kl + 8);
            }
            #pragma unroll
            for (int mt = 0; mt < 4; mt++) {
                const bf16* ar = bA_h + (wm + mt * 16 + g) * ASTR + k0 + 2 * t;
                uint32_t ah0 = *(const uint32_t*)ar;
                uint32_t ah1 = *(const uint32_t*)(ar + 8 * ASTR);
                uint32_t ah2 = *(const uint32_t*)(ar + 8);
                uint32_t ah3 = *(const uint32_t*)(ar + 8 * ASTR + 8);
                const bf16* al = bA_l + (wm + mt * 16 + g) * ASTR + k0 + 2 * t;
                uint32_t al0 = *(const uint32_t*)al;
                uint32_t al1 = *(const uint32_t*)(al + 8 * ASTR);
                uint32_t al2 = *(const uint32_t*)(al + 8);
                uint32_t al3 = *(const uint32_t*)(al + 8 * ASTR + 8);
                #pragma unroll
                for (int nt = 0; nt < 4; nt++) {
                    mma16816(acc[mt][nt], ah0, ah1, ah2, ah3, bh[nt][0], bh[nt][1]);
                    mma16816(acc[mt][nt], ah0, ah1, ah2, ah3, bl[nt][0], bl[nt][1]);
                    mma16816(acc[mt][nt], al0, al1, al2, al3, bh[nt][0], bh[nt][1]);
                }
            }
        }
        __syncthreads();
        if (c + 2 < NCH) stage(c + 2);
    }

    // Epilogue
    #pragma unroll
    for (int mt = 0; mt < 4; mt++) {
        int r0 = m0 + wm + mt * 16 + g;
        #pragma unroll
        for (int nt = 0; nt < 4; nt++) {
            int cc = n0 + wn + nt * 8 + 2 * t;
            float b0 = bias[cc], b1 = bias[cc + 1];
            float v0 = acc[mt][nt][0] + b0, v1 = acc[mt][nt][1] + b1;
            float v2 = acc[mt][nt][2] + b0, v3 = acc[mt][nt][3] + b1;
            if (SPLIT_OUT) {
                uint32_t h01, l01, h23, l23;
                packsplit(v0, v1, h01, l01);
                packsplit(v2, v3, h23, l23);
                *(uint32_t*)(Ch + (size_t)r0 * N + cc)       = h01;
                *(uint32_t*)(Cl + (size_t)r0 * N + cc)       = l01;
                *(uint32_t*)(Ch + (size_t)(r0 + 8) * N + cc) = h23;
                *(uint32_t*)(Cl + (size_t)(r0 + 8) * N + cc) = l23;
            } else {
                *(float2*)(C + (size_t)r0 * N + cc)       = make_float2(v0, v1);
                *(float2*)(C + (size_t)(r0 + 8) * N + cc) = make_float2(v2, v3);
            }
        }
    }
}

// ---------------------------------------------------------------------------
// Flash attention, 3xBF16, FA2-style. Block = 128 queries of one (b,h).
// 8 warps, each owns 16 q-rows x full 64-key range; S/P stay in registers.
// K: direct LDS b-frags; V: ldmatrix.x4.trans; K/V double-buffered cp.async.
// ---------------------------------------------------------------------------
#define KSTR 72
#define FTE  (64 * KSTR)      // 4608 elems per array
#define FTB  (FTE * 2)        // 9216 bytes

__global__ __launch_bounds__(256) void flash_bf16_kernel(
    const bf16* __restrict__ qkvh, const bf16* __restrict__ qkvl,
    bf16* __restrict__ attnh, bf16* __restrict__ attnl)
{
    extern __shared__ bf16 smf[];
    const uint32_t sm0 = smem_u32(smf);

    const int tid = threadIdx.x;
    const int lane = tid & 31, wid = tid >> 5;
    const int g = lane >> 2, t = lane & 3;

    const int bq = gridDim.x - 1 - blockIdx.x;   // heavy blocks launch first
    const int q0 = bq * 128;
    const int bh_ = blockIdx.y;
    const int b = bh_ / HH, h = bh_ % HH;
    const int J = 2 * bq + 1;

    // ---- Q fragments (hi/lo) in registers ----
    const int qrow = q0 + wid * 16 + g;
    const bf16* qp_h = qkvh + (size_t)(b * SS + qrow) * NQKV + h * HDD;
    const bf16* qp_l = qkvl + (size_t)(b * SS + qrow) * NQKV + h * HDD;
    uint32_t qh[4][4], ql[4][4];
    #pragma unroll
    for (int s = 0; s < 4; s++) {
        int k = s * 16 + 2 * t;
        qh[s][0] = *(const uint32_t*)(qp_h + k);
        qh[s][1] = *(const uint32_t*)(qp_h + 8 * NQKV + k);
        qh[s][2] = *(const uint32_t*)(qp_h + k + 8);
        qh[s][3] = *(const uint32_t*)(qp_h + 8 * NQKV + k + 8);
        ql[s][0] = *(const uint32_t*)(qp_l + k);
        ql[s][1] = *(const uint32_t*)(qp_l + 8 * NQKV + k);
        ql[s][2] = *(const uint32_t*)(qp_l + k + 8);
        ql[s][3] = *(const uint32_t*)(qp_l + 8 * NQKV + k + 8);
    }

    float od[8][4];
    #pragma unroll
    for (int nt = 0; nt < 8; nt++)
        #pragma unroll
        for (int r = 0; r < 4; r++) od[nt][r] = 0.f;
    float m0v = -1e30f, m1v = -1e30f, l0v = 0.f, l1v = 0.f;

    auto stage = [&](int j) {
        const uint32_t bb = sm0 + (j & 1) * 4 * FTB;
        const int tok0 = (b * SS + j * 64) * NQKV + DD + h * HDD;
        #pragma unroll
        for (int i = 0; i < 2; i++) {
            int idx = tid + i * 256;
            int r = idx >> 3, c = idx & 7;
            uint32_t doff = r * 144 + c * 16;
            int sK = tok0 + r * NQKV + c * 8;
            int sV = sK + DD;
            cp16(bb + doff,           qkvh + sK);   // Kh
            cp16(bb + FTB + doff,     qkvl + sK);   // Kl
            cp16(bb + 2 * FTB + doff, qkvh + sV);   // Vh
            cp16(bb + 3 * FTB + doff, qkvl + sV);   // Vl
        }
        CP_COMMIT();
    };

    stage(0);
    const float CLOG = 0.18033688011112042f;   // 0.125 * log2(e)

    for (int j = 0; j <= J; j++) {
        if (j < J) stage(j + 1);
        if (j < J) { CP_WAIT1(); } else { CP_WAIT0(); }
        __syncthreads();

        const bf16* Kh_s = smf + (size_t)(j & 1) * 4 * FTE;
        const bf16* Kl_s = Kh_s + FTE;
        const uint32_t vh_base = sm0 + (j & 1) * 4 * FTB + 2 * FTB;

        // ---- S = Q @ K^T (3xBF16) ----
        float sc[8][4];
        #pragma unroll
        for (int nt = 0; nt < 8; nt++)
            #pragma unroll
            for (int r = 0; r < 4; r++) sc[nt][r] = 0.f;

        #pragma unroll
        for (int s = 0; s < 4; s++) {
            const int k0 = s * 16;
            #pragma unroll
            for (int nt = 0; nt < 8; nt++) {
                const bf16* kr = Kh_s + (nt * 8 + g) * KSTR + k0 + 2 * t;
                uint32_t b0h = *(const uint32_t*)kr;
                uint32_t b1h = *(const uint32_t*)(kr + 8);
                const bf16* kl = Kl_s + (nt * 8 + g) * KSTR + k0 + 2 * t;
                uint32_t b0l = *(const uint32_t*)kl;
                uint32_t b1l = *(const uint32_t*)(kl + 8);
                mma16816(sc[nt], qh[s][0], qh[s][1], qh[s][2], qh[s][3], b0h, b1h);
                mma16816(sc[nt], qh[s][0], qh[s][1], qh[s][2], qh[s][3], b0l, b1l);
                mma16816(sc[nt], ql[s][0], ql[s][1], ql[s][2], ql[s][3], b0h, b1h);
            }
        }

        // ---- scale + mask + online softmax (base-2) ----
        const bool maskTile = (j >= 2 * bq);
        const int key_base = j * 64;
        float tmax0 = -1e30f, tmax1 = -1e30f;
        #pragma unroll
        for (int nt = 0; nt < 8; nt++) {
            #pragma unroll
            for (int i = 0; i < 4; i++) {
                float v = sc[nt][i] * CLOG;
                if (maskTile) {
                    int key = key_base + nt * 8 + 2 * t + (i & 1);
                    int qq = qrow + ((i >= 2) ? 8 : 0);
                    if (key > qq) v = -1e30f;
                }
                sc[nt][i] = v;
                if (i < 2) tmax0 = fmaxf(tmax0, v);
                else       tmax1 = fmaxf(tmax1, v);
            }
        }
        tmax0 = fmaxf(tmax0, __shfl_xor_sync(0xffffffffu, tmax0, 1));
        tmax0 = fmaxf(tmax0, __shfl_xor_sync(0xffffffffu, tmax0, 2));
        tmax1 = fmaxf(tmax1, __shfl_xor_sync(0xffffffffu, tmax1, 1));
        tmax1 = fmaxf(tmax1, __shfl_xor_sync(0xffffffffu, tmax1, 2));

        float mn0 = fmaxf(m0v, tmax0), mn1 = fmaxf(m1v, tmax1);
        float a0 = ex2f(m0v - mn0), a1 = ex2f(m1v - mn1);
        m0v = mn0; m1v = mn1;

        float s0 = 0.f, s1 = 0.f;
        #pragma unroll
        for (int nt = 0; nt < 8; nt++) {
            float p0 = ex2f(sc[nt][0] - mn0);
            float p1 = ex2f(sc[nt][1] - mn0);
            float p2 = ex2f(sc[nt][2] - mn1);
            float p3 = ex2f(sc[nt][3] - mn1);
            sc[nt][0] = p0; sc[nt][1] = p1; sc[nt][2] = p2; sc[nt][3] = p3;
            s0 += p0 + p1; s1 += p2 + p3;
        }
        s0 += __shfl_xor_sync(0xffffffffu, s0, 1);
        s0 += __shfl_xor_sync(0xffffffffu, s0, 2);
        s1 += __shfl_xor_sync(0xffffffffu, s1, 1);
        s1 += __shfl_xor_sync(0xffffffffu, s1, 2);
        l0v = l0v * a0 + s0;
        l1v = l1v * a1 + s1;

        #pragma unroll
        for (int nt = 0; nt < 8; nt++) {
            od[nt][0] *= a0; od[nt][1] *= a0;
            od[nt][2] *= a1; od[nt][3] *= a1;
        }

        // ---- pack P into bf16 hi/lo A-fragments (register-only) ----
        uint32_t ph[4][4], pl[4][4];
        #pragma unroll
        for (int s2 = 0; s2 < 4; s2++) {
            int e = 2 * s2, o = 2 * s2 + 1;
            packsplit(sc[e][0], sc[e][1], ph[s2][0], pl[s2][0]);
            packsplit(sc[e][2], sc[e][3], ph[s2][1], pl[s2][1]);
            packsplit(sc[o][0], sc[o][1], ph[s2][2], pl[s2][2]);
            packsplit(sc[o][2], sc[o][3], ph[s2][3], pl[s2][3]);
        }

        // ---- O += P @ V (V b-frags via ldmatrix.trans) ----
        #pragma unroll
        for (int s2 = 0; s2 < 4; s2++) {
            uint32_t rowcol = (s2 * 16 + (lane & 15)) * 144 + ((lane & 16) ? 16 : 0);
            #pragma unroll
            for (int dtb = 0; dtb < 4; dtb++) {
                uint32_t addr = vh_base + rowcol + dtb * 32;
                uint32_t vh4[4], vl4[4];
                ldsm4t(vh4, addr);
                ldsm4t(vl4, addr + FTB);
                mma16816(od[2 * dtb],     ph[s2][0], ph[s2][1], ph[s2][2], ph[s2][3], vh4[0], vh4[1]);
                mma16816(od[2 * dtb],     ph[s2][0], ph[s2][1], ph[s2][2], ph[s2][3], vl4[0], vl4[1]);
                mma16816(od[2 * dtb],     pl[s2][0], pl[s2][1], pl[s2][2], pl[s2][3], vh4[0], vh4[1]);
                mma16816(od[2 * dtb + 1], ph[s2][0], ph[s2][1], ph[s2][2], ph[s2][3], vh4[2], vh4[3]);
                mma16816(od[2 * dtb + 1], ph[s2][0], ph[s2][1], ph[s2][2], ph[s2][3], vl4[2], vl4[3]);
                mma16816(od[2 * dtb + 1], pl[s2][0], pl[s2][1], pl[s2][2], pl[s2][3], vh4[2], vh4[3]);
            }
        }
        __syncthreads();
    }

    // ---- epilogue: normalize, split, write attn hi/lo ----
    float inv0 = 1.f / l0v, inv1 = 1.f / l1v;
    bf16* oh = attnh + (size_t)(b * SS + qrow) * DD + h * HDD;
    bf16* ol = attnl + (size_t)(b * SS + qrow) * DD + h * HDD;
    #pragma unroll
    for (int nt = 0; nt < 8; nt++) {
        int cc = nt * 8 + 2 * t;
        float v0 = od[nt][0] * inv0, v1 = od[nt][1] * inv0;
        float v2 = od[nt][2] * inv1, v3 = od[nt][3] * inv1;
        uint32_t h01, l01, h23, l23;
        packsplit(v0, v1, h01, l01);
        packsplit(v2, v3, h23, l23);
        *(uint32_t*)(oh + cc)          = h01;
        *(uint32_t*)(ol + cc)          = l01;
        *(uint32_t*)(oh + 8 * DD + cc) = h23;
        *(uint32_t*)(ol + 8 * DD + cc) = l23;
    }
}

// ---------------------------------------------------------------------------
// Launch
// ---------------------------------------------------------------------------
extern "C" void kernel_launch(void* const* d_in, const int* in_sizes, int n_in,
                              void* d_out, int out_size)
{
    const float* X    = (const float*)d_in[0];
    const float* Wqkv = (const float*)d_in[1];
    const float* bqkv = (const float*)d_in[2];
    const float* Wout = (const float*)d_in[3];
    const float* bout = (const float*)d_in[4];
    float* out = (float*)d_out;

    bf16 *qkvh, *qkvl, *attnh, *attnl, *Xh, *Xl, *Bqh, *Bql, *Boh, *Bol;
    cudaGetSymbolAddress((void**)&qkvh,  g_qkvh);
    cudaGetSymbolAddress((void**)&qkvl,  g_qkvl);
    cudaGetSymbolAddress((void**)&attnh, g_attnh);
    cudaGetSymbolAddress((void**)&attnl, g_attnl);
    cudaGetSymbolAddress((void**)&Xh,    g_Xh);
    cudaGetSymbolAddress((void**)&Xl,    g_Xl);
    cudaGetSymbolAddress((void**)&Bqh,   g_Bqh);
    cudaGetSymbolAddress((void**)&Bql,   g_Bql);
    cudaGetSymbolAddress((void**)&Boh,   g_Boh);
    cudaGetSymbolAddress((void**)&Bol,   g_Bol);

    const int gemm_smem  = 2 * 4 * ABYTES;   // 81920
    const int flash_smem = 2 * 4 * FTB;      // 73728

    cudaFuncSetAttribute(gemm_bf16_kernel<true>,
                         cudaFuncAttributeMaxDynamicSharedMemorySize, gemm_smem);
    cudaFuncSetAttribute(gemm_bf16_kernel<false>,
                         cudaFuncAttributeMaxDynamicSharedMemorySize, gemm_smem);
    cudaFuncSetAttribute(flash_bf16_kernel,
                         cudaFuncAttributeMaxDynamicSharedMemorySize, flash_smem);

    // Prep: split X, transpose+split weights
    {
        int n4 = MM * DD / 4;
        split_pair_kernel<<<(n4 + 255) / 256, 256>>>(X, Xh, Xl, n4);
        dim3 blk(32, 8);
        transpose_split_kernel<<<dim3(NQKV / 32, DD / 32), blk>>>(Wqkv, Bqh, Bql, DD, NQKV);
        transpose_split_kernel<<<dim3(DD / 32, DD / 32), blk>>>(Wout, Boh, Bol, DD, DD);
    }

    // 1) QKV = X @ Wqkv + bqkv   (writes split bf16 directly)
    {
        dim3 grid(NQKV / 128, MM / 128);   // (18, 32)
        gemm_bf16_kernel<true><<<grid, 256, gemm_smem>>>(
            Xh, Xl, Bqh, Bql, bqkv, nullptr, qkvh, qkvl, MM, NQKV, DD);
    }

    // 2) Flash attention (128-query blocks; writes split attn directly)
    {
        dim3 grid(SS / 128, BB * HH);      // (16, 24)
        flash_bf16_kernel<<<grid, 256, flash_smem>>>(qkvh, qkvl, attnh, attnl);
    }

    // 3) out = attn @ Wout + bout  (fp32 out)
    {
        dim3 grid(DD / 128, MM / 128);     // (6, 32)
        gemm_bf16_kernel<false><<<grid, 256, gemm_smem>>>(
            attnh, attnl, Boh, Bol, bout, out, nullptr, nullptr, MM, DD, DD);
    }
}

// round 7
// speedup vs baseline: 2.8526x; 1.0256x over previous
#include <cuda_runtime.h>
#include <cuda_bf16.h>
#include <math.h>
#include <cstdint>

// Problem constants
#define BB   2
#define SS   2048
#define DD   768
#define HH   12
#define HDD  64
#define MM   (BB * SS)        // 4096
#define NQKV (3 * DD)         // 2304

typedef __nv_bfloat16 bf16;

// Scratch (__device__ globals; no allocation allowed)
__device__ bf16 g_qkvh[MM * NQKV];
__device__ bf16 g_qkvl[MM * NQKV];
__device__ bf16 g_attnh[MM * DD];
__device__ bf16 g_attnl[MM * DD];
__device__ bf16 g_Xh[MM * DD];
__device__ bf16 g_Xl[MM * DD];
__device__ bf16 g_Bqh[NQKV * DD];
__device__ bf16 g_Bql[NQKV * DD];
__device__ bf16 g_Boh[DD * DD];
__device__ bf16 g_Bol[DD * DD];

// ---------------------------------------------------------------------------
// Helpers
// ---------------------------------------------------------------------------
__device__ __forceinline__ uint32_t smem_u32(const void* p) {
    uint32_t a;
    asm("{ .reg .u64 t; cvta.to.shared.u64 t, %1; cvt.u32.u64 %0, t; }" : "=r"(a) : "l"(p));
    return a;
}

__device__ __forceinline__ float ex2f(float x) {
    float r;
    asm("ex2.approx.ftz.f32 %0, %1;" : "=f"(r) : "f"(x));
    return r;
}

__device__ __forceinline__ uint32_t cvt_pack_bf16(float lo, float hi) {
    uint32_t r;
    asm("cvt.rn.bf16x2.f32 %0, %1, %2;" : "=r"(r) : "f"(hi), "f"(lo));
    return r;
}

__device__ __forceinline__ void packsplit(float x0, float x1, uint32_t& hi, uint32_t& lo) {
    uint32_t u0 = __float_as_uint(x0) & 0xFFFF0000u;
    uint32_t u1 = __float_as_uint(x1) & 0xFFFF0000u;
    uint32_t h;
    asm("prmt.b32 %0, %1, %2, 0x7632;" : "=r"(h) : "r"(u0), "r"(u1));
    hi = h;
    float r0 = x0 - __uint_as_float(u0);
    float r1 = x1 - __uint_as_float(u1);
    lo = cvt_pack_bf16(r0, r1);
}

__device__ __forceinline__ void mma16816(float* c,
                                         uint32_t a0, uint32_t a1, uint32_t a2, uint32_t a3,
                                         uint32_t b0, uint32_t b1) {
    asm volatile(
        "mma.sync.aligned.m16n8k16.row.col.f32.bf16.bf16.f32 "
        "{%0,%1,%2,%3}, {%4,%5,%6,%7}, {%8,%9}, {%0,%1,%2,%3};\n"
        : "+f"(c[0]), "+f"(c[1]), "+f"(c[2]), "+f"(c[3])
        : "r"(a0), "r"(a1), "r"(a2), "r"(a3), "r"(b0), "r"(b1));
}

__device__ __forceinline__ void ldsm4t(uint32_t* r, uint32_t saddr) {
    asm volatile("ldmatrix.sync.aligned.m8n8.x4.trans.shared.b16 {%0,%1,%2,%3}, [%4];"
                 : "=r"(r[0]), "=r"(r[1]), "=r"(r[2]), "=r"(r[3]) : "r"(saddr));
}

__device__ __forceinline__ void cp16(uint32_t dst, const void* src) {
    asm volatile("cp.async.cg.shared.global [%0], [%1], 16;" :: "r"(dst), "l"(src));
}
#define CP_COMMIT() asm volatile("cp.async.commit_group;" ::: "memory")
#define CP_WAIT0()  asm volatile("cp.async.wait_group 0;" ::: "memory")
#define CP_WAIT1()  asm volatile("cp.async.wait_group 1;" ::: "memory")

// ---------------------------------------------------------------------------
// Prep kernels
// ---------------------------------------------------------------------------
__global__ void split_pair_kernel(const float* __restrict__ x,
                                  bf16* __restrict__ h, bf16* __restrict__ l, int n4)
{
    int i = blockIdx.x * blockDim.x + threadIdx.x;
    if (i < n4) {
        float4 v = ((const float4*)x)[i];
        uint32_t h01, l01, h23, l23;
        packsplit(v.x, v.y, h01, l01);
        packsplit(v.z, v.w, h23, l23);
        ((uint2*)h)[i] = make_uint2(h01, h23);
        ((uint2*)l)[i] = make_uint2(l01, l23);
    }
}

__global__ void transpose_split_kernel(const float* __restrict__ W,
                                       bf16* __restrict__ Th, bf16* __restrict__ Tl,
                                       int Kd, int Nd)
{
    __shared__ float tile[32][33];
    int n0 = blockIdx.x * 32, k0 = blockIdx.y * 32;
    int tx = threadIdx.x, ty = threadIdx.y;   // (32, 8)
    #pragma unroll
    for (int i = 0; i < 4; i++)
        tile[ty + i * 8][tx] = W[(size_t)(k0 + ty + i * 8) * Nd + n0 + tx];
    __syncthreads();
    int idx = ty * 32 + tx;
    int n = idx >> 3, kp = idx & 7;
    #pragma unroll
    for (int w = 0; w < 2; w++) {
        int k2 = (kp + w * 8) * 2;
        uint32_t hh, ll;
        packsplit(tile[k2][n], tile[k2 + 1][n], hh, ll);
        *(uint32_t*)(Th + (size_t)(n0 + n) * Kd + k0 + k2) = hh;
        *(uint32_t*)(Tl + (size_t)(n0 + n) * Kd + k0 + k2) = ll;
    }
}

// ---------------------------------------------------------------------------
// GEMM (3xBF16): C[M,N] = A[M,K] @ Bt[N,K]^T + bias
// 2 CTAs/SM (regs capped at 128).
// ---------------------------------------------------------------------------
#define ASTR 40
#define TILEE (128 * ASTR)
#define ABYTES (TILEE * 2)

template<bool SPLIT_OUT>
__global__ __launch_bounds__(256, 2) void gemm_bf16_kernel(
    const bf16* __restrict__ Ah_g, const bf16* __restrict__ Al_g,
    const bf16* __restrict__ Bh_g, const bf16* __restrict__ Bl_g,
    const float* __restrict__ bias,
    float* __restrict__ C, bf16* __restrict__ Ch, bf16* __restrict__ Cl,
    int M, int N, int K)
{
    extern __shared__ bf16 smb[];
    const uint32_t sm0 = smem_u32(smb);

    const int tid = threadIdx.x;
    const int lane = tid & 31, warp = tid >> 5;
    const int g = lane >> 2, t = lane & 3;
    const int m0 = blockIdx.y * 128, n0 = blockIdx.x * 128;
    const int wm = (warp >> 2) * 64, wn = (warp & 3) * 32;

    float acc[4][4][4];
    #pragma unroll
    for (int mt = 0; mt < 4; mt++)
        #pragma unroll
        for (int nt = 0; nt < 4; nt++)
            #pragma unroll
            for (int r = 0; r < 4; r++) acc[mt][nt][r] = 0.f;

    const int NCH = K / 32;

    auto stage = [&](int ch) {
        const int kb = ch * 32;
        const uint32_t bb = sm0 + (ch & 1) * 4 * ABYTES;
        #pragma unroll
        for (int i = 0; i < 2; i++) {
            int idx = tid + i * 256;
            int r = idx >> 2, cc = idx & 3;
            uint32_t doff = r * 80 + cc * 16;
            cp16(bb + doff,              Ah_g + (size_t)(m0 + r) * K + kb + cc * 8);
            cp16(bb + ABYTES + doff,     Al_g + (size_t)(m0 + r) * K + kb + cc * 8);
            cp16(bb + 2 * ABYTES + doff, Bh_g + (size_t)(n0 + r) * K + kb + cc * 8);
            cp16(bb + 3 * ABYTES + doff, Bl_g + (size_t)(n0 + r) * K + kb + cc * 8);
        }
        CP_COMMIT();
    };

    stage(0);
    stage(1);

    for (int c = 0; c < NCH; c++) {
        if (c == NCH - 1) { CP_WAIT0(); } else { CP_WAIT1(); }
        __syncthreads();

        const bf16* bA_h = smb + (size_t)(c & 1) * 4 * TILEE;
        const bf16* bA_l = bA_h + TILEE;
        const bf16* bB_h = bA_h + 2 * TILEE;
        const bf16* bB_l = bA_h + 3 * TILEE;

        #pragma unroll
        for (int st = 0; st < 2; st++) {
            const int k0 = st * 16;
            uint32_t bh[4][2], bl[4][2];
            #pragma unroll
            for (int nt = 0; nt < 4; nt++) {
                const bf16* kr = bB_h + (wn + nt * 8 + g) * ASTR + k0 + 2 * t;
                bh[nt][0] = *(const uint32_t*)kr;
                bh[nt][1] = *(const uint32_t*)(kr + 8);
                const bf16* kl = bB_l + (wn + nt * 8 + g) * ASTR + k0 + 2 * t;
                bl[nt][0] = *(const uint32_t*)kl;
                bl[nt][1] = *(const uint32_t*)(kl + 8);
            }
            #pragma unroll
            for (int mt = 0; mt < 4; mt++) {
                const bf16* ar = bA_h + (wm + mt * 16 + g) * ASTR + k0 + 2 * t;
                uint32_t ah0 = *(const uint32_t*)ar;
                uint32_t ah1 = *(const uint32_t*)(ar + 8 * ASTR);
                uint32_t ah2 = *(const uint32_t*)(ar + 8);
                uint32_t ah3 = *(const uint32_t*)(ar + 8 * ASTR + 8);
                const bf16* al = bA_l + (wm + mt * 16 + g) * ASTR + k0 + 2 * t;
                uint32_t al0 = *(const uint32_t*)al;
                uint32_t al1 = *(const uint32_t*)(al + 8 * ASTR);
                uint32_t al2 = *(const uint32_t*)(al + 8);
                uint32_t al3 = *(const uint32_t*)(al + 8 * ASTR + 8);
                #pragma unroll
                for (int nt = 0; nt < 4; nt++) {
                    mma16816(acc[mt][nt], ah0, ah1, ah2, ah3, bh[nt][0], bh[nt][1]);
                    mma16816(acc[mt][nt], ah0, ah1, ah2, ah3, bl[nt][0], bl[nt][1]);
                    mma16816(acc[mt][nt], al0, al1, al2, al3, bh[nt][0], bh[nt][1]);
                }
            }
        }
        __syncthreads();
        if (c + 2 < NCH) stage(c + 2);
    }

    #pragma unroll
    for (int mt = 0; mt < 4; mt++) {
        int r0 = m0 + wm + mt * 16 + g;
        #pragma unroll
        for (int nt = 0; nt < 4; nt++) {
            int cc = n0 + wn + nt * 8 + 2 * t;
            float b0 = bias[cc], b1 = bias[cc + 1];
            float v0 = acc[mt][nt][0] + b0, v1 = acc[mt][nt][1] + b1;
            float v2 = acc[mt][nt][2] + b0, v3 = acc[mt][nt][3] + b1;
            if (SPLIT_OUT) {
                uint32_t h01, l01, h23, l23;
                packsplit(v0, v1, h01, l01);
                packsplit(v2, v3, h23, l23);
                *(uint32_t*)(Ch + (size_t)r0 * N + cc)       = h01;
                *(uint32_t*)(Cl + (size_t)r0 * N + cc)       = l01;
                *(uint32_t*)(Ch + (size_t)(r0 + 8) * N + cc) = h23;
                *(uint32_t*)(Cl + (size_t)(r0 + 8) * N + cc) = l23;
            } else {
                *(float2*)(C + (size_t)r0 * N + cc)       = make_float2(v0, v1);
                *(float2*)(C + (size_t)(r0 + 8) * N + cc) = make_float2(v2, v3);
            }
        }
    }
}

// ---------------------------------------------------------------------------
// Flash attention, 3xBF16, FA2-style. Block = 128 queries of one (b,h).
// Q hi/lo staged in smem (frees ~32 regs) -> 2 CTAs/SM.
// ---------------------------------------------------------------------------
#define KSTR 72
#define FTE  (64 * KSTR)      // 4608 elems per K/V array
#define FTB  (FTE * 2)        // 9216 bytes
#define QTE  (128 * KSTR)     // 9216 elems per Q array
#define QTB  (QTE * 2)        // 18432 bytes

__global__ __launch_bounds__(256, 2) void flash_bf16_kernel(
    const bf16* __restrict__ qkvh, const bf16* __restrict__ qkvl,
    bf16* __restrict__ attnh, bf16* __restrict__ attnl)
{
    extern __shared__ bf16 smf[];
    const uint32_t sm0 = smem_u32(smf);

    const int tid = threadIdx.x;
    const int lane = tid & 31, wid = tid >> 5;
    const int g = lane >> 2, t = lane & 3;

    const int bq = gridDim.x - 1 - blockIdx.x;
    const int q0 = bq * 128;
    const int bh_ = blockIdx.y;
    const int b = bh_ / HH, h = bh_ % HH;
    const int J = 2 * bq + 1;

    const bf16* Qh_s = smf + 8 * FTE;          // after 2 buffers x 4 KV arrays
    const bf16* Ql_s = Qh_s + QTE;
    const uint32_t qsm_h = sm0 + 8 * FTB;
    const uint32_t qsm_l = qsm_h + QTB;

    // ---- stage Q (hi/lo) into smem via cp.async ----
    {
        const int tok0 = (b * SS + q0) * NQKV + h * HDD;
        #pragma unroll
        for (int i = 0; i < 4; i++) {
            int idx = tid + i * 256;
            int r = idx >> 3, c = idx & 7;
            uint32_t doff = r * 144 + c * 16;
            int src = tok0 + r * NQKV + c * 8;
            cp16(qsm_h + doff, qkvh + src);
            cp16(qsm_l + doff, qkvl + src);
        }
        CP_COMMIT();
    }

    const int qrow = q0 + wid * 16 + g;

    float od[8][4];
    #pragma unroll
    for (int nt = 0; nt < 8; nt++)
        #pragma unroll
        for (int r = 0; r < 4; r++) od[nt][r] = 0.f;
    float m0v = -1e30f, m1v = -1e30f, l0v = 0.f, l1v = 0.f;

    auto stage = [&](int j) {
        const uint32_t bb = sm0 + (j & 1) * 4 * FTB;
        const int tok0 = (b * SS + j * 64) * NQKV + DD + h * HDD;
        #pragma unroll
        for (int i = 0; i < 2; i++) {
            int idx = tid + i * 256;
            int r = idx >> 3, c = idx & 7;
            uint32_t doff = r * 144 + c * 16;
            int sK = tok0 + r * NQKV + c * 8;
            int sV = sK + DD;
            cp16(bb + doff,           qkvh + sK);
            cp16(bb + FTB + doff,     qkvl + sK);
            cp16(bb + 2 * FTB + doff, qkvh + sV);
            cp16(bb + 3 * FTB + doff, qkvl + sV);
        }
        CP_COMMIT();
    };

    stage(0);
    const float CLOG = 0.18033688011112042f;   // 0.125 * log2(e)

    for (int j = 0; j <= J; j++) {
        if (j < J) stage(j + 1);
        if (j < J) { CP_WAIT1(); } else { CP_WAIT0(); }
        __syncthreads();

        const bf16* Kh_s = smf + (size_t)(j & 1) * 4 * FTE;
        const bf16* Kl_s = Kh_s + FTE;
        const uint32_t vh_base = sm0 + (j & 1) * 4 * FTB + 2 * FTB;

        // ---- S = Q @ K^T (3xBF16), Q frags from smem ----
        float sc[8][4];
        #pragma unroll
        for (int nt = 0; nt < 8; nt++)
            #pragma unroll
            for (int r = 0; r < 4; r++) sc[nt][r] = 0.f;

        #pragma unroll
        for (int s = 0; s < 4; s++) {
            const int k0 = s * 16;
            const bf16* qr_h = Qh_s + (wid * 16 + g) * KSTR + k0 + 2 * t;
            uint32_t qh0 = *(const uint32_t*)qr_h;
            uint32_t qh1 = *(const uint32_t*)(qr_h + 8 * KSTR);
            uint32_t qh2 = *(const uint32_t*)(qr_h + 8);
            uint32_t qh3 = *(const uint32_t*)(qr_h + 8 * KSTR + 8);
            const bf16* qr_l = Ql_s + (wid * 16 + g) * KSTR + k0 + 2 * t;
            uint32_t ql0 = *(const uint32_t*)qr_l;
            uint32_t ql1 = *(const uint32_t*)(qr_l + 8 * KSTR);
            uint32_t ql2 = *(const uint32_t*)(qr_l + 8);
            uint32_t ql3 = *(const uint32_t*)(qr_l + 8 * KSTR + 8);
            #pragma unroll
            for (int nt = 0; nt < 8; nt++) {
                const bf16* kr = Kh_s + (nt * 8 + g) * KSTR + k0 + 2 * t;
                uint32_t b0h = *(const uint32_t*)kr;
                uint32_t b1h = *(const uint32_t*)(kr + 8);
                const bf16* kl = Kl_s + (nt * 8 + g) * KSTR + k0 + 2 * t;
                uint32_t b0l = *(const uint32_t*)kl;
                uint32_t b1l = *(const uint32_t*)(kl + 8);
                mma16816(sc[nt], qh0, qh1, qh2, qh3, b0h, b1h);
                mma16816(sc[nt], qh0, qh1, qh2, qh3, b0l, b1l);
                mma16816(sc[nt], ql0, ql1, ql2, ql3, b0h, b1h);
            }
        }

        // ---- scale + mask + online softmax (base-2) ----
        const bool maskTile = (j >= 2 * bq);
        const int key_base = j * 64;
        float tmax0 = -1e30f, tmax1 = -1e30f;
        #pragma unroll
        for (int nt = 0; nt < 8; nt++) {
            #pragma unroll
            for (int i = 0; i < 4; i++) {
                float v = sc[nt][i] * CLOG;
                if (maskTile) {
                    int key = key_base + nt * 8 + 2 * t + (i & 1);
                    int qq = qrow + ((i >= 2) ? 8 : 0);
                    if (key > qq) v = -1e30f;
                }
                sc[nt][i] = v;
                if (i < 2) tmax0 = fmaxf(tmax0, v);
                else       tmax1 = fmaxf(tmax1, v);
            }
        }
        tmax0 = fmaxf(tmax0, __shfl_xor_sync(0xffffffffu, tmax0, 1));
        tmax0 = fmaxf(tmax0, __shfl_xor_sync(0xffffffffu, tmax0, 2));
        tmax1 = fmaxf(tmax1, __shfl_xor_sync(0xffffffffu, tmax1, 1));
        tmax1 = fmaxf(tmax1, __shfl_xor_sync(0xffffffffu, tmax1, 2));

        float mn0 = fmaxf(m0v, tmax0), mn1 = fmaxf(m1v, tmax1);
        float a0 = ex2f(m0v - mn0), a1 = ex2f(m1v - mn1);
        m0v = mn0; m1v = mn1;

        float s0 = 0.f, s1 = 0.f;
        #pragma unroll
        for (int nt = 0; nt < 8; nt++) {
            float p0 = ex2f(sc[nt][0] - mn0);
            float p1 = ex2f(sc[nt][1] - mn0);
            float p2 = ex2f(sc[nt][2] - mn1);
            float p3 = ex2f(sc[nt][3] - mn1);
            sc[nt][0] = p0; sc[nt][1] = p1; sc[nt][2] = p2; sc[nt][3] = p3;
            s0 += p0 + p1; s1 += p2 + p3;
        }
        s0 += __shfl_xor_sync(0xffffffffu, s0, 1);
        s0 += __shfl_xor_sync(0xffffffffu, s0, 2);
        s1 += __shfl_xor_sync(0xffffffffu, s1, 1);
        s1 += __shfl_xor_sync(0xffffffffu, s1, 2);
        l0v = l0v * a0 + s0;
        l1v = l1v * a1 + s1;

        #pragma unroll
        for (int nt = 0; nt < 8; nt++) {
            od[nt][0] *= a0; od[nt][1] *= a0;
            od[nt][2] *= a1; od[nt][3] *= a1;
        }

        // ---- pack P into bf16 hi/lo A-fragments (register-only) ----
        uint32_t ph[4][4], pl[4][4];
        #pragma unroll
        for (int s2 = 0; s2 < 4; s2++) {
            int e = 2 * s2, o = 2 * s2 + 1;
            packsplit(sc[e][0], sc[e][1], ph[s2][0], pl[s2][0]);
            packsplit(sc[e][2], sc[e][3], ph[s2][1], pl[s2][1]);
            packsplit(sc[o][0], sc[o][1], ph[s2][2], pl[s2][2]);
            packsplit(sc[o][2], sc[o][3], ph[s2][3], pl[s2][3]);
        }

        // ---- O += P @ V (V b-frags via ldmatrix.trans) ----
        #pragma unroll
        for (int s2 = 0; s2 < 4; s2++) {
            uint32_t rowcol = (s2 * 16 + (lane & 15)) * 144 + ((lane & 16) ? 16 : 0);
            #pragma unroll
            for (int dtb = 0; dtb < 4; dtb++) {
                uint32_t addr = vh_base + rowcol + dtb * 32;
                uint32_t vh4[4], vl4[4];
                ldsm4t(vh4, addr);
                ldsm4t(vl4, addr + FTB);
                mma16816(od[2 * dtb],     ph[s2][0], ph[s2][1], ph[s2][2], ph[s2][3], vh4[0], vh4[1]);
                mma16816(od[2 * dtb],     ph[s2][0], ph[s2][1], ph[s2][2], ph[s2][3], vl4[0], vl4[1]);
                mma16816(od[2 * dtb],     pl[s2][0], pl[s2][1], pl[s2][2], pl[s2][3], vh4[0], vh4[1]);
                mma16816(od[2 * dtb + 1], ph[s2][0], ph[s2][1], ph[s2][2], ph[s2][3], vh4[2], vh4[3]);
                mma16816(od[2 * dtb + 1], ph[s2][0], ph[s2][1], ph[s2][2], ph[s2][3], vl4[2], vl4[3]);
                mma16816(od[2 * dtb + 1], pl[s2][0], pl[s2][1], pl[s2][2], pl[s2][3], vh4[2], vh4[3]);
            }
        }
        __syncthreads();
    }

    // ---- epilogue: normalize, split, write attn hi/lo ----
    float inv0 = 1.f / l0v, inv1 = 1.f / l1v;
    bf16* oh = attnh + (size_t)(b * SS + qrow) * DD + h * HDD;
    bf16* ol = attnl + (size_t)(b * SS + qrow) * DD + h * HDD;
    #pragma unroll
    for (int nt = 0; nt < 8; nt++) {
        int cc = nt * 8 + 2 * t;
        float v0 = od[nt][0] * inv0, v1 = od[nt][1] * inv0;
        float v2 = od[nt][2] * inv1, v3 = od[nt][3] * inv1;
        uint32_t h01, l01, h23, l23;
        packsplit(v0, v1, h01, l01);
        packsplit(v2, v3, h23, l23);
        *(uint32_t*)(oh + cc)          = h01;
        *(uint32_t*)(ol + cc)          = l01;
        *(uint32_t*)(oh + 8 * DD + cc) = h23;
        *(uint32_t*)(ol + 8 * DD + cc) = l23;
    }
}

// ---------------------------------------------------------------------------
// Launch
// ---------------------------------------------------------------------------
extern "C" void kernel_launch(void* const* d_in, const int* in_sizes, int n_in,
                              void* d_out, int out_size)
{
    const float* X    = (const float*)d_in[0];
    const float* Wqkv = (const float*)d_in[1];
    const float* bqkv = (const float*)d_in[2];
    const float* Wout = (const float*)d_in[3];
    const float* bout = (const float*)d_in[4];
    float* out = (float*)d_out;

    bf16 *qkvh, *qkvl, *attnh, *attnl, *Xh, *Xl, *Bqh, *Bql, *Boh, *Bol;
    cudaGetSymbolAddress((void**)&qkvh,  g_qkvh);
    cudaGetSymbolAddress((void**)&qkvl,  g_qkvl);
    cudaGetSymbolAddress((void**)&attnh, g_attnh);
    cudaGetSymbolAddress((void**)&attnl, g_attnl);
    cudaGetSymbolAddress((void**)&Xh,    g_Xh);
    cudaGetSymbolAddress((void**)&Xl,    g_Xl);
    cudaGetSymbolAddress((void**)&Bqh,   g_Bqh);
    cudaGetSymbolAddress((void**)&Bql,   g_Bql);
    cudaGetSymbolAddress((void**)&Boh,   g_Boh);
    cudaGetSymbolAddress((void**)&Bol,   g_Bol);

    const int gemm_smem  = 2 * 4 * ABYTES;            // 81920
    const int flash_smem = 2 * 4 * FTB + 2 * QTB;     // 110592

    cudaFuncSetAttribute(gemm_bf16_kernel<true>,
                         cudaFuncAttributeMaxDynamicSharedMemorySize, gemm_smem);
    cudaFuncSetAttribute(gemm_bf16_kernel<false>,
                         cudaFuncAttributeMaxDynamicSharedMemorySize, gemm_smem);
    cudaFuncSetAttribute(flash_bf16_kernel,
                         cudaFuncAttributeMaxDynamicSharedMemorySize, flash_smem);

    // Prep
    {
        int n4 = MM * DD / 4;
        split_pair_kernel<<<(n4 + 255) / 256, 256>>>(X, Xh, Xl, n4);
        dim3 blk(32, 8);
        transpose_split_kernel<<<dim3(NQKV / 32, DD / 32), blk>>>(Wqkv, Bqh, Bql, DD, NQKV);
        transpose_split_kernel<<<dim3(DD / 32, DD / 32), blk>>>(Wout, Boh, Bol, DD, DD);
    }

    // 1) QKV = X @ Wqkv + bqkv
    {
        dim3 grid(NQKV / 128, MM / 128);
        gemm_bf16_kernel<true><<<grid, 256, gemm_smem>>>(
            Xh, Xl, Bqh, Bql, bqkv, nullptr, qkvh, qkvl, MM, NQKV, DD);
    }

    // 2) Flash attention
    {
        dim3 grid(SS / 128, BB * HH);
        flash_bf16_kernel<<<grid, 256, flash_smem>>>(qkvh, qkvl, attnh, attnl);
    }

    // 3) out = attn @ Wout + bout
    {
        dim3 grid(DD / 128, MM / 128);
        gemm_bf16_kernel<false><<<grid, 256, gemm_smem>>>(
            attnh, attnl, Boh, Bol, bout, out, nullptr, nullptr, MM, DD, DD);
    }
}